// round 10
// baseline (speedup 1.0000x reference)
#include <cuda_runtime.h>
#include <cuda_fp16.h>
#include <math.h>
#include <stdint.h>

#define BB 2
#define SS 2048
#define DD 768
#define PP 16

// -------- scratch --------
__device__ __half g_x[BB * SS * DD];
__device__ __half g_wT[3 * DD * DD];         // [z][n][k]
__device__ __half g_q[BB * SS * DD];
__device__ __half g_k[BB * SS * DD];
__device__ __half g_vT[BB * DD * SS];        // [b][d][s]
__device__ float  g_sc[BB * SS * SS];
__device__ __half g_p[BB * SS * SS];
__device__ int    g_idx[BB * PP];

__global__ void decode_idx_kernel(const int* __restrict__ raw) {
    bool is64 = (raw[1] == 0);
    int t = threadIdx.x;
    if (t < BB * PP) g_idx[t] = is64 ? raw[2 * t] : raw[t];
}

// -------- cp.async --------
__device__ __forceinline__ void cp16(uint32_t s, const void* g) {
    asm volatile("cp.async.cg.shared.global [%0], [%1], 16;\n" :: "r"(s), "l"(g));
}
__device__ __forceinline__ void cp16z(uint32_t s, const void* g, bool v) {
    int sz = v ? 16 : 0;
    asm volatile("cp.async.cg.shared.global [%0], [%1], 16, %2;\n" :: "r"(s), "l"(g), "r"(sz));
}
#define CP_COMMIT asm volatile("cp.async.commit_group;\n")
#define CP_WAIT1  asm volatile("cp.async.wait_group 1;\n")

// -------- mma / ldmatrix --------
__device__ __forceinline__ void mma_fp16(float* c, const uint32_t* a, const uint32_t* b) {
    asm volatile(
        "mma.sync.aligned.m16n8k16.row.col.f32.f16.f16.f32 "
        "{%0,%1,%2,%3},{%4,%5,%6,%7},{%8,%9},{%0,%1,%2,%3};\n"
        : "+f"(c[0]), "+f"(c[1]), "+f"(c[2]), "+f"(c[3])
        : "r"(a[0]), "r"(a[1]), "r"(a[2]), "r"(a[3]), "r"(b[0]), "r"(b[1]));
}
__device__ __forceinline__ void ldsm4(uint32_t& r0, uint32_t& r1, uint32_t& r2,
                                      uint32_t& r3, uint32_t addr) {
    asm volatile("ldmatrix.sync.aligned.m8n8.x4.shared.b16 {%0,%1,%2,%3}, [%4];"
                 : "=r"(r0), "=r"(r1), "=r"(r2), "=r"(r3) : "r"(addr));
}

// -------- prep --------
__global__ __launch_bounds__(256) void trunc_x_kernel(const float* __restrict__ x)
{
    const int NX = BB * SS * DD;
    int stride = gridDim.x * blockDim.x;
    for (int i = blockIdx.x * blockDim.x + threadIdx.x; i < NX / 4; i += stride) {
        float4 v = *(const float4*)&x[i * 4];
        __half2 h0 = __floats2half2_rn(v.x, v.y);
        __half2 h1 = __floats2half2_rn(v.z, v.w);
        *(uint2*)&g_x[i * 4] = make_uint2(*(uint32_t*)&h0, *(uint32_t*)&h1);
    }
}

__global__ __launch_bounds__(256) void transw_kernel(
    const float* __restrict__ Wq, const float* __restrict__ Wk, const float* __restrict__ Wv)
{
    __shared__ float t[32][33];
    const int z = blockIdx.z;
    const float* W = (z == 0) ? Wq : (z == 1) ? Wk : Wv;
    const int n0 = blockIdx.x * 32, k0 = blockIdx.y * 32;
    for (int i = threadIdx.y; i < 32; i += 8)
        t[i][threadIdx.x] = W[(size_t)(k0 + i) * DD + n0 + threadIdx.x];
    __syncthreads();
    for (int i = threadIdx.y; i < 32; i += 8)
        g_wT[(size_t)z * DD * DD + (size_t)(n0 + i) * DD + k0 + threadIdx.x] =
            __float2half(t[threadIdx.x][i]);
}

// ============================================================
// fp16 GEMM: D[128,256] = A[128,K] @ B[256,K]^T
// BK=64 halfs (128B rows, SW128 swizzle), 3-stage cp.async,
// ldmatrix. 8 warps (2x4), warp tile 64x64.
// MODE 2 (AV): segment [start,end); out-of-segment columns of
// the A (probs) tile are zeroed in smem on boundary k-tiles.
// ============================================================
#define TILE_A_B 16384                 // A tile: 128 x 128B
#define TILE_B_B 32768                 // B tile: 256 x 128B
#define STG_B    (TILE_A_B + TILE_B_B) // 49152
#define SMEM_TOTAL (3 * STG_B)         // 147456

extern __shared__ char dsm[];

template<int MODE>
__global__ __launch_bounds__(256, 1) void hgemm_kernel(
    const float* __restrict__ bq, const float* __restrict__ bk,
    const float* __restrict__ bv, float* __restrict__ out_av)
{
    const int tid  = threadIdx.x;
    const int lane = tid & 31;
    const int warp = tid >> 5;
    const int wm = warp >> 2, wn = warp & 3;
    const int m0 = blockIdx.y * 128;
    const int n0 = blockIdx.x * 256;
    const int c2 = (lane & 3) * 2;
    const int qr = lane >> 2;

    const __half* Ab; const __half* Bb;
    int lda, ldb, base = 0, start = 0, end = 1 << 30, KT;
    if (MODE == 0) {
        Ab = g_x; lda = DD;
        Bb = g_wT + (size_t)blockIdx.z * DD * DD; ldb = DD;
        KT = DD / 64;
    } else if (MODE == 1) {
        Ab = g_q + (size_t)blockIdx.z * SS * DD; lda = DD;
        Bb = g_k + (size_t)blockIdx.z * SS * DD; ldb = DD;
        KT = DD / 64;
    } else {
        int bp = blockIdx.z, b = bp / PP, p = bp % PP;
        start = g_idx[b * PP + p];
        end   = (p == PP - 1) ? SS : g_idx[b * PP + p + 1];
        base  = start & ~63;
        Ab = g_p + (size_t)b * SS * SS; lda = SS;
        Bb = g_vT + (size_t)b * DD * SS; ldb = SS;
        KT = (end - base + 63) / 64;
    }

    const uint32_t smb = (uint32_t)__cvta_generic_to_shared(dsm);
    float acc[4][8][4] = {};

    const int lrow = ((lane >> 3) & 1) * 8 + (lane & 7);
    const int lcadd = lane >> 4;

    auto issue = [&](int kt) {
        if (kt < KT) {
            uint32_t sa = smb + (kt % 3) * STG_B;
            uint32_t sb = sa + TILE_A_B;
            int k0 = base + kt * 64;
            #pragma unroll
            for (int i = 0; i < 4; ++i) {
                int id = tid + i * 256;
                int r = id >> 3, c = id & 7;
                uint32_t sw = (uint32_t)(r * 128 + ((c ^ (r & 7)) * 16));
                int j = k0 + c * 8;
                if (MODE == 2) cp16z(sa + sw, Ab + (size_t)(m0 + r) * lda + j, j < SS);
                else           cp16 (sa + sw, Ab + (size_t)(m0 + r) * lda + j);
            }
            #pragma unroll
            for (int i = 0; i < 8; ++i) {
                int id = tid + i * 256;
                int r = id >> 3, c = id & 7;
                uint32_t sw = (uint32_t)(r * 128 + ((c ^ (r & 7)) * 16));
                int j = k0 + c * 8;
                if (MODE == 2) cp16z(sb + sw, Bb + (size_t)(n0 + r) * ldb + j, j < SS);
                else           cp16 (sb + sw, Bb + (size_t)(n0 + r) * ldb + j);
            }
        }
        CP_COMMIT;
    };

    issue(0); issue(1);

    for (int kt = 0; kt < KT; ++kt) {
        CP_WAIT1;
        __syncthreads();

        uint32_t sa = smb + (kt % 3) * STG_B;
        uint32_t sb = sa + TILE_A_B;

        // Boundary masking for AV: zero A-tile columns outside [start,end).
        // Columns outside the segment hold OTHER patches' probabilities.
        if (MODE == 2) {
            int rel = base + kt * 64;
            int lo = start - rel;            // >0 only on first k-tile
            int hi = end - rel;              // <64 only on last k-tile
            if (lo > 0 || hi < 64) {
                int lo_c = lo > 0 ? lo : 0;
                int hi_c = hi < 64 ? hi : 64;
                char* sAh = dsm + (kt % 3) * STG_B;
                for (int idx = tid; idx < 128 * 64; idx += 256) {
                    int r = idx >> 6, c = idx & 63;
                    if (c < lo_c || c >= hi_c) {
                        uint32_t off = (uint32_t)(r * 128 + c * 2);
                        uint32_t sw = off ^ ((off >> 3) & 0x70);
                        *(__half*)(sAh + sw) = __ushort_as_half(0);
                    }
                }
                __syncthreads();
            }
        }

        issue(kt + 2);

        #pragma unroll
        for (int ks = 0; ks < 64; ks += 16) {
            const int kc = ks >> 3;
            uint32_t a[4][4], b[8][2];
            #pragma unroll
            for (int mi = 0; mi < 4; ++mi) {
                int row = wm * 64 + mi * 16 + lrow;
                uint32_t addr = sa + row * 128 + (((kc + lcadd) ^ (row & 7)) * 16);
                ldsm4(a[mi][0], a[mi][1], a[mi][2], a[mi][3], addr);
            }
            #pragma unroll
            for (int pr = 0; pr < 4; ++pr) {
                int nrow = wn * 64 + pr * 16 + lrow;
                uint32_t addr = sb + nrow * 128 + (((kc + lcadd) ^ (nrow & 7)) * 16);
                uint32_t r0, r1, r2, r3;
                ldsm4(r0, r1, r2, r3, addr);
                b[pr * 2][0] = r0;     b[pr * 2][1] = r2;
                b[pr * 2 + 1][0] = r1; b[pr * 2 + 1][1] = r3;
            }
            #pragma unroll
            for (int mi = 0; mi < 4; ++mi)
                #pragma unroll
                for (int ni = 0; ni < 8; ++ni)
                    mma_fp16(acc[mi][ni], a[mi], b[ni]);
        }
    }

    // ---- epilogue ----
    #pragma unroll
    for (int mi = 0; mi < 4; ++mi) {
        #pragma unroll
        for (int ni = 0; ni < 8; ++ni) {
            int r = m0 + wm * 64 + mi * 16 + qr;
            int c = n0 + wn * 64 + ni * 8 + c2;
            float v00 = acc[mi][ni][0], v01 = acc[mi][ni][1];
            float v10 = acc[mi][ni][2], v11 = acc[mi][ni][3];
            if (MODE == 0) {
                const int z = blockIdx.z;
                const float* bias = (z == 0) ? bq : (z == 1) ? bk : bv;
                float b0 = bias[c], b1 = bias[c + 1];
                if (z < 2) {
                    __half* outp = (z == 0) ? g_q : g_k;
                    __half2 h0 = __floats2half2_rn(v00 + b0, v01 + b1);
                    __half2 h1 = __floats2half2_rn(v10 + b0, v11 + b1);
                    *(uint32_t*)&outp[(size_t)r * DD + c] = *(uint32_t*)&h0;
                    *(uint32_t*)&outp[(size_t)(r + 8) * DD + c] = *(uint32_t*)&h1;
                } else {
                    int b_i = r >> 11, s = r & (SS - 1);
                    int b_j = (r + 8) >> 11, s2 = (r + 8) & (SS - 1);
                    g_vT[((size_t)b_i * DD + c) * SS + s]      = __float2half(v00 + b0);
                    g_vT[((size_t)b_i * DD + c + 1) * SS + s]  = __float2half(v01 + b1);
                    g_vT[((size_t)b_j * DD + c) * SS + s2]     = __float2half(v10 + b0);
                    g_vT[((size_t)b_j * DD + c + 1) * SS + s2] = __float2half(v11 + b1);
                }
            } else if (MODE == 1) {
                const float scale = 0.03608439182435161f;
                float* Sc = g_sc + (size_t)blockIdx.z * SS * SS;
                float2 o0 = {v00 * scale, v01 * scale};
                float2 o1 = {v10 * scale, v11 * scale};
                *(float2*)&Sc[(size_t)r * SS + c] = o0;
                *(float2*)&Sc[(size_t)(r + 8) * SS + c] = o1;
            } else {
                const int bp = blockIdx.z;
                float2 o0 = {v00, v01};
                float2 o1 = {v10, v11};
                *(float2*)&out_av[((size_t)bp * SS + r) * DD + c] = o0;
                *(float2*)&out_av[((size_t)bp * SS + r + 8) * DD + c] = o1;
            }
        }
    }
}

// ============================================================
// segment softmax: fp32 scores in, fp16 probs out
// ============================================================
__global__ __launch_bounds__(256) void softmax_kernel()
{
    const int b = blockIdx.z;
    const int p = blockIdx.y;
    const int warp = threadIdx.x >> 5;
    const int lane = threadIdx.x & 31;
    const int q = blockIdx.x * 8 + warp;

    const int start = g_idx[b * PP + p];
    const int end   = (p == PP - 1) ? SS : g_idx[b * PP + p + 1];

    const float* row = g_sc + ((size_t)b * SS + q) * SS;
    __half* prow = g_p + ((size_t)b * SS + q) * SS;

    float m = -INFINITY;
    for (int j = start + lane; j < end; j += 32) m = fmaxf(m, row[j]);
    #pragma unroll
    for (int o = 16; o; o >>= 1) m = fmaxf(m, __shfl_xor_sync(0xFFFFFFFFu, m, o));

    float s = 0.f;
    for (int j = start + lane; j < end; j += 32) s += __expf(row[j] - m);
    #pragma unroll
    for (int o = 16; o; o >>= 1) s += __shfl_xor_sync(0xFFFFFFFFu, s, o);

    float inv = 1.f / s;
    for (int j = start + lane; j < end; j += 32)
        prow[j] = __float2half(__expf(row[j] - m) * inv);
}

// ============================================================
extern "C" void kernel_launch(void* const* d_in, const int* in_sizes, int n_in,
                              void* d_out, int out_size)
{
    const float* x   = (const float*)d_in[0];
    const int*   raw = (const int*)d_in[1];
    const float* Wq  = (const float*)d_in[2];
    const float* bq  = (const float*)d_in[3];
    const float* Wk  = (const float*)d_in[4];
    const float* bk  = (const float*)d_in[5];
    const float* Wv  = (const float*)d_in[6];
    const float* bv  = (const float*)d_in[7];
    float* out = (float*)d_out;

    cudaFuncSetAttribute(hgemm_kernel<0>, cudaFuncAttributeMaxDynamicSharedMemorySize, SMEM_TOTAL);
    cudaFuncSetAttribute(hgemm_kernel<1>, cudaFuncAttributeMaxDynamicSharedMemorySize, SMEM_TOTAL);
    cudaFuncSetAttribute(hgemm_kernel<2>, cudaFuncAttributeMaxDynamicSharedMemorySize, SMEM_TOTAL);

    decode_idx_kernel<<<1, 64>>>(raw);
    trunc_x_kernel<<<512, 256>>>(x);
    transw_kernel<<<dim3(DD / 32, DD / 32, 3), dim3(32, 8)>>>(Wq, Wk, Wv);
    hgemm_kernel<0><<<dim3(DD / 256, (BB * SS) / 128, 3), 256, SMEM_TOTAL>>>(bq, bk, bv, out);
    hgemm_kernel<1><<<dim3(SS / 256, SS / 128, BB), 256, SMEM_TOTAL>>>(bq, bk, bv, out);
    softmax_kernel<<<dim3(SS / 8, PP, BB), 256>>>();
    hgemm_kernel<2><<<dim3(DD / 256, SS / 128, BB * PP), 256, SMEM_TOTAL>>>(bq, bk, bv, out);
}

// round 11
// speedup vs baseline: 1.0852x; 1.0852x over previous
#include <cuda_runtime.h>
#include <cuda_fp16.h>
#include <math.h>
#include <stdint.h>

#define BB 2
#define SS 2048
#define DD 768
#define PP 16
#define SP (SS + 64)                 // padded prob-row stride

// -------- scratch --------
__device__ __half g_x[BB * SS * DD];
__device__ __half g_wT[3 * DD * DD];          // [z][n][k]
__device__ __half g_q[BB * SS * DD];
__device__ __half g_k[BB * SS * DD];
__device__ __half g_vT[BB * DD * SS];         // [b][d][s]
__device__ float  g_sc[BB * SS * SS];
__device__ __half g_p2[(size_t)BB * PP * SS * SP];  // per-patch prob planes (padded)
__device__ int    g_idx[BB * PP];

__global__ void decode_idx_kernel(const int* __restrict__ raw) {
    bool is64 = (raw[1] == 0);
    int t = threadIdx.x;
    if (t < BB * PP) g_idx[t] = is64 ? raw[2 * t] : raw[t];
}

// -------- cp.async --------
__device__ __forceinline__ void cp16(uint32_t s, const void* g) {
    asm volatile("cp.async.cg.shared.global [%0], [%1], 16;\n" :: "r"(s), "l"(g));
}
__device__ __forceinline__ void cp16z(uint32_t s, const void* g, bool v) {
    int sz = v ? 16 : 0;
    asm volatile("cp.async.cg.shared.global [%0], [%1], 16, %2;\n" :: "r"(s), "l"(g), "r"(sz));
}
#define CP_COMMIT asm volatile("cp.async.commit_group;\n")
#define CP_WAIT1  asm volatile("cp.async.wait_group 1;\n")

// -------- mma / ldmatrix --------
__device__ __forceinline__ void mma_fp16(float* c, const uint32_t* a, const uint32_t* b) {
    asm volatile(
        "mma.sync.aligned.m16n8k16.row.col.f32.f16.f16.f32 "
        "{%0,%1,%2,%3},{%4,%5,%6,%7},{%8,%9},{%0,%1,%2,%3};\n"
        : "+f"(c[0]), "+f"(c[1]), "+f"(c[2]), "+f"(c[3])
        : "r"(a[0]), "r"(a[1]), "r"(a[2]), "r"(a[3]), "r"(b[0]), "r"(b[1]));
}
__device__ __forceinline__ void ldsm4(uint32_t& r0, uint32_t& r1, uint32_t& r2,
                                      uint32_t& r3, uint32_t addr) {
    asm volatile("ldmatrix.sync.aligned.m8n8.x4.shared.b16 {%0,%1,%2,%3}, [%4];"
                 : "=r"(r0), "=r"(r1), "=r"(r2), "=r"(r3) : "r"(addr));
}

// -------- prep --------
__global__ __launch_bounds__(256) void trunc_x_kernel(const float* __restrict__ x)
{
    const int NX = BB * SS * DD;
    int stride = gridDim.x * blockDim.x;
    for (int i = blockIdx.x * blockDim.x + threadIdx.x; i < NX / 4; i += stride) {
        float4 v = *(const float4*)&x[i * 4];
        __half2 h0 = __floats2half2_rn(v.x, v.y);
        __half2 h1 = __floats2half2_rn(v.z, v.w);
        *(uint2*)&g_x[i * 4] = make_uint2(*(uint32_t*)&h0, *(uint32_t*)&h1);
    }
}

__global__ __launch_bounds__(256) void transw_kernel(
    const float* __restrict__ Wq, const float* __restrict__ Wk, const float* __restrict__ Wv)
{
    __shared__ float t[32][33];
    const int z = blockIdx.z;
    const float* W = (z == 0) ? Wq : (z == 1) ? Wk : Wv;
    const int n0 = blockIdx.x * 32, k0 = blockIdx.y * 32;
    for (int i = threadIdx.y; i < 32; i += 8)
        t[i][threadIdx.x] = W[(size_t)(k0 + i) * DD + n0 + threadIdx.x];
    __syncthreads();
    for (int i = threadIdx.y; i < 32; i += 8)
        g_wT[(size_t)z * DD * DD + (size_t)(n0 + i) * DD + k0 + threadIdx.x] =
            __float2half(t[threadIdx.x][i]);
}

// ============================================================
// fp16 GEMM: D[128,128] = A[128,K] @ B[128,K]^T
// BK=64 halfs (128B rows, SW128 swizzle), 3-stage cp.async,
// ldmatrix. 8 warps (2x4), warp tile 64x32. 2 CTA/SM.
// MODE 2 (AV): reads pre-cleaned per-patch prob plane - no masking.
// ============================================================
#define TILE_B (128 * 128)           // bytes per tile
#define STG_B  (2 * TILE_B)
#define SMEM_TOTAL (3 * STG_B)       // 98304

extern __shared__ char dsm[];

template<int MODE>
__global__ __launch_bounds__(256, 2) void hgemm_kernel(
    const float* __restrict__ bq, const float* __restrict__ bk,
    const float* __restrict__ bv, float* __restrict__ out_av)
{
    const int tid  = threadIdx.x;
    const int lane = tid & 31;
    const int warp = tid >> 5;
    const int wm = warp >> 2, wn = warp & 3;
    const int m0 = blockIdx.y * 128;
    const int n0 = blockIdx.x * 128;
    const int c2 = (lane & 3) * 2;
    const int qr = lane >> 2;

    const __half* Ab; const __half* Bb;
    int lda, ldb, base = 0, KT;
    if (MODE == 0) {
        Ab = g_x; lda = DD;
        Bb = g_wT + (size_t)blockIdx.z * DD * DD; ldb = DD;
        KT = DD / 64;
    } else if (MODE == 1) {
        Ab = g_q + (size_t)blockIdx.z * SS * DD; lda = DD;
        Bb = g_k + (size_t)blockIdx.z * SS * DD; ldb = DD;
        KT = DD / 64;
    } else {
        int bp = blockIdx.z, b = bp / PP, p = bp % PP;
        int start = g_idx[b * PP + p];
        int end   = (p == PP - 1) ? SS : g_idx[b * PP + p + 1];
        base  = start & ~63;
        Ab = g_p2 + (size_t)bp * SS * SP; lda = SP;   // per-patch plane, padded
        Bb = g_vT + (size_t)b * DD * SS; ldb = SS;
        KT = (end - base + 63) / 64;
    }

    const uint32_t smb = (uint32_t)__cvta_generic_to_shared(dsm);
    float acc[4][4][4] = {};

    const int lrow = ((lane >> 3) & 1) * 8 + (lane & 7);
    const int lcadd = lane >> 4;

    auto issue = [&](int kt) {
        if (kt < KT) {
            uint32_t sa = smb + (kt % 3) * STG_B;
            uint32_t sb = sa + TILE_B;
            int k0 = base + kt * 64;
            #pragma unroll
            for (int i = 0; i < 4; ++i) {
                int id = tid + i * 256;              // 0..1023
                int r = id >> 3, c = id & 7;
                uint32_t sw = (uint32_t)(r * 128 + ((c ^ (r & 7)) * 16));
                int j = k0 + c * 8;
                // A: always safe (padded plane in MODE 2, full rows otherwise)
                cp16(sa + sw, Ab + (size_t)(m0 + r) * lda + j);
                // B: guard j<SS only in MODE 2 (vT rows are SS long)
                if (MODE == 2) cp16z(sb + sw, Bb + (size_t)(n0 + r) * ldb + j, j < SS);
                else           cp16 (sb + sw, Bb + (size_t)(n0 + r) * ldb + j);
            }
        }
        CP_COMMIT;
    };

    issue(0); issue(1);

    for (int kt = 0; kt < KT; ++kt) {
        CP_WAIT1;
        __syncthreads();

        uint32_t sa = smb + (kt % 3) * STG_B;
        uint32_t sb = sa + TILE_B;

        issue(kt + 2);

        #pragma unroll
        for (int ks = 0; ks < 64; ks += 16) {
            const int kc = ks >> 3;                 // 0,2,4,6
            uint32_t a[4][4], b[4][2];
            #pragma unroll
            for (int mi = 0; mi < 4; ++mi) {
                int row = wm * 64 + mi * 16 + lrow;
                uint32_t addr = sa + row * 128 + (((kc + lcadd) ^ (row & 7)) * 16);
                ldsm4(a[mi][0], a[mi][1], a[mi][2], a[mi][3], addr);
            }
            #pragma unroll
            for (int pr = 0; pr < 2; ++pr) {
                int nrow = wn * 32 + pr * 16 + lrow;
                uint32_t addr = sb + nrow * 128 + (((kc + lcadd) ^ (nrow & 7)) * 16);
                uint32_t r0, r1, r2, r3;
                ldsm4(r0, r1, r2, r3, addr);
                b[pr * 2][0] = r0;     b[pr * 2][1] = r2;
                b[pr * 2 + 1][0] = r1; b[pr * 2 + 1][1] = r3;
            }
            #pragma unroll
            for (int mi = 0; mi < 4; ++mi)
                #pragma unroll
                for (int ni = 0; ni < 4; ++ni)
                    mma_fp16(acc[mi][ni], a[mi], b[ni]);
        }
    }

    // ---- epilogue ----
    #pragma unroll
    for (int mi = 0; mi < 4; ++mi) {
        #pragma unroll
        for (int ni = 0; ni < 4; ++ni) {
            int r = m0 + wm * 64 + mi * 16 + qr;
            int c = n0 + wn * 32 + ni * 8 + c2;
            float v00 = acc[mi][ni][0], v01 = acc[mi][ni][1];
            float v10 = acc[mi][ni][2], v11 = acc[mi][ni][3];
            if (MODE == 0) {
                const int z = blockIdx.z;
                const float* bias = (z == 0) ? bq : (z == 1) ? bk : bv;
                float b0 = bias[c], b1 = bias[c + 1];
                if (z < 2) {
                    __half* outp = (z == 0) ? g_q : g_k;
                    __half2 h0 = __floats2half2_rn(v00 + b0, v01 + b1);
                    __half2 h1 = __floats2half2_rn(v10 + b0, v11 + b1);
                    *(uint32_t*)&outp[(size_t)r * DD + c] = *(uint32_t*)&h0;
                    *(uint32_t*)&outp[(size_t)(r + 8) * DD + c] = *(uint32_t*)&h1;
                } else {
                    int b_i = r >> 11, s = r & (SS - 1);
                    int b_j = (r + 8) >> 11, s2 = (r + 8) & (SS - 1);
                    g_vT[((size_t)b_i * DD + c) * SS + s]      = __float2half(v00 + b0);
                    g_vT[((size_t)b_i * DD + c + 1) * SS + s]  = __float2half(v01 + b1);
                    g_vT[((size_t)b_j * DD + c) * SS + s2]     = __float2half(v10 + b0);
                    g_vT[((size_t)b_j * DD + c + 1) * SS + s2] = __float2half(v11 + b1);
                }
            } else if (MODE == 1) {
                const float scale = 0.03608439182435161f;
                float* Sc = g_sc + (size_t)blockIdx.z * SS * SS;
                float2 o0 = {v00 * scale, v01 * scale};
                float2 o1 = {v10 * scale, v11 * scale};
                *(float2*)&Sc[(size_t)r * SS + c] = o0;
                *(float2*)&Sc[(size_t)(r + 8) * SS + c] = o1;
            } else {
                const int bp = blockIdx.z;
                float2 o0 = {v00, v01};
                float2 o1 = {v10, v11};
                *(float2*)&out_av[((size_t)bp * SS + r) * DD + c] = o0;
                *(float2*)&out_av[((size_t)bp * SS + r + 8) * DD + c] = o1;
            }
        }
    }
}

// ============================================================
// segment softmax: fp32 scores in; writes fp16 probs into the
// per-patch padded plane AND zeroes the 64-aligned boundary bands,
// so AV needs no masking.
// ============================================================
__global__ __launch_bounds__(256) void softmax_kernel()
{
    const int b = blockIdx.z;
    const int p = blockIdx.y;
    const int warp = threadIdx.x >> 5;
    const int lane = threadIdx.x & 31;
    const int q = blockIdx.x * 8 + warp;

    const int start = g_idx[b * PP + p];
    const int end   = (p == PP - 1) ? SS : g_idx[b * PP + p + 1];
    const int base  = start & ~63;
    const int kend  = base + ((end - base + 63) & ~63);   // <= SS+63 < SP

    const float* row = g_sc + ((size_t)b * SS + q) * SS;
    __half* prow = g_p2 + ((size_t)(b * PP + p) * SS + q) * SP;

    float m = -INFINITY;
    for (int j = start + lane; j < end; j += 32) m = fmaxf(m, row[j]);
    #pragma unroll
    for (int o = 16; o; o >>= 1) m = fmaxf(m, __shfl_xor_sync(0xFFFFFFFFu, m, o));

    float s = 0.f;
    for (int j = start + lane; j < end; j += 32) s += __expf(row[j] - m);
    #pragma unroll
    for (int o = 16; o; o >>= 1) s += __shfl_xor_sync(0xFFFFFFFFu, s, o);

    float inv = 1.f / s;
    for (int j = start + lane; j < end; j += 32)
        prow[j] = __float2half(__expf(row[j] - m) * inv);

    // zero boundary bands [base,start) and [end,kend)
    for (int j = base + lane; j < start; j += 32) prow[j] = __ushort_as_half(0);
    for (int j = end + lane; j < kend; j += 32)   prow[j] = __ushort_as_half(0);
}

// ============================================================
extern "C" void kernel_launch(void* const* d_in, const int* in_sizes, int n_in,
                              void* d_out, int out_size)
{
    const float* x   = (const float*)d_in[0];
    const int*   raw = (const int*)d_in[1];
    const float* Wq  = (const float*)d_in[2];
    const float* bq  = (const float*)d_in[3];
    const float* Wk  = (const float*)d_in[4];
    const float* bk  = (const float*)d_in[5];
    const float* Wv  = (const float*)d_in[6];
    const float* bv  = (const float*)d_in[7];
    float* out = (float*)d_out;

    cudaFuncSetAttribute(hgemm_kernel<0>, cudaFuncAttributeMaxDynamicSharedMemorySize, SMEM_TOTAL);
    cudaFuncSetAttribute(hgemm_kernel<1>, cudaFuncAttributeMaxDynamicSharedMemorySize, SMEM_TOTAL);
    cudaFuncSetAttribute(hgemm_kernel<2>, cudaFuncAttributeMaxDynamicSharedMemorySize, SMEM_TOTAL);

    decode_idx_kernel<<<1, 64>>>(raw);
    trunc_x_kernel<<<512, 256>>>(x);
    transw_kernel<<<dim3(DD / 32, DD / 32, 3), dim3(32, 8)>>>(Wq, Wk, Wv);
    hgemm_kernel<0><<<dim3(DD / 128, (BB * SS) / 128, 3), 256, SMEM_TOTAL>>>(bq, bk, bv, out);
    hgemm_kernel<1><<<dim3(SS / 128, SS / 128, BB), 256, SMEM_TOTAL>>>(bq, bk, bv, out);
    softmax_kernel<<<dim3(SS / 8, PP, BB), 256>>>();
    hgemm_kernel<2><<<dim3(DD / 128, SS / 128, BB * PP), 256, SMEM_TOTAL>>>(bq, bk, bv, out);
}